// round 15
// baseline (speedup 1.0000x reference)
#include <cuda_runtime.h>

// GAEChamferLoss: B=16, C=3, N=4096, mask in {0,1}. Single fused persistent
// kernel: init -> compact -> pairwise-min -> reduce -> finalize, separated by
// software grid barriers (444 co-resident blocks, 3 per SM).
// d = |x|^2 + |y|^2 - 2 x.y; |y|^2 folded into the FMA chain, |x|^2 added
// after the min. Hot loop: packed fma.rn.f32x2 with 8 outers/thread (4 packed
// pairs) -> 2.75 instr/pair and 0.25 LDS/pair. Inner tile pre-duplicated in
// smem so broadcasts need no pack movs. Phase 2 is a work-stealing queue.

#define BB 16
#define NN 4096
#define BIGV 1e10f

#define NBLK 444                   // 3 x 148 (all resident on 148/152-SM parts)
#define NTHR 256
#define IS 64                      // inner splits
#define OC 2                       // outer chunks of 2048 (covers cnt<=4096)
#define OPT 8                      // outers per thread (4 packed pairs)
#define OUTER_PER_BLOCK (NTHR * OPT)   // 2048
#define MAX_INNER ((NN + IS - 1) / IS) // 64 worst case
#define NUNITS (OC * 2 * IS * BB)      // 4096

typedef unsigned long long u64;

__device__ __forceinline__ u64 pack2(float lo, float hi) {
    u64 r; asm("mov.b64 %0, {%1, %2};" : "=l"(r) : "f"(lo), "f"(hi)); return r;
}
__device__ __forceinline__ u64 fma2(u64 a, u64 b, u64 c) {
    u64 d;
    asm("fma.rn.f32x2 %0, %1, %2, %3;" : "=l"(d) : "l"(a), "l"(b), "l"(c));
    return d;
}
__device__ __forceinline__ void unpack2(u64 v, float& lo, float& hi) {
    asm("mov.b64 {%0, %1}, %2;" : "=f"(lo), "=f"(hi) : "l"(v));
}

// Scratch (device globals — no allocations allowed)
__device__ float d_cx[BB * 3 * NN];
__device__ float d_cy[BB * 3 * NN];
__device__ float d_nx[BB * NN];
__device__ float d_ny[BB * NN];
__device__ int   d_cnt[BB];
__device__ __align__(16) float d_mins[2 * BB * NN];
__device__ float d_sums[2 * BB];
__device__ int   d_unit;                   // work-steal cursor
__device__ unsigned d_bar_arrive;          // static 0
__device__ volatile unsigned d_bar_gen;    // monotonically increasing

__device__ __forceinline__ void grid_barrier() {
    __syncthreads();
    __threadfence();
    if (threadIdx.x == 0) {
        unsigned gen = d_bar_gen;
        if (atomicAdd(&d_bar_arrive, 1u) == NBLK - 1) {
            atomicExch(&d_bar_arrive, 0u);
            __threadfence();
            d_bar_gen = gen + 1;
        } else {
            while (d_bar_gen == gen) { }
        }
    }
    __syncthreads();
}

__global__ __launch_bounds__(NTHR, 3)
void k_fused(const float* __restrict__ x, const float* __restrict__ y,
             const int* __restrict__ mask, float* __restrict__ out)
{
    const int tid = threadIdx.x;
    const int bid = blockIdx.x;
    // per inner point: two float4s = {-2a,-2a,-2c,-2c} and {-2e,-2e, n, n}
    __shared__ float4 sIn[2 * MAX_INNER];          // 2 KB
    __shared__ float sRed[NTHR / 32];
    __shared__ int sU;

    // ---------- Phase 0: init (cross-phase stores via .cg = L2 only) -------
    if (bid == 0) {
        if (tid < 2 * BB) __stcg(&d_sums[tid], 0.f);
        if (tid < BB) __stcg(&d_cnt[tid], 0);
        if (tid == 0) __stcg(&d_unit, 0);
    }
    {
        int idx = bid * NTHR + tid;                 // float2 slots: 65536 total
        if (idx < BB * NN)
            __stcg((float2*)&d_mins[idx * 2], make_float2(BIGV, BIGV));
    }
    grid_barrier();

    // ---------- Phase 1: warp-aggregated compaction + norms ----------------
    {
        const int g = bid * NTHR + tid;             // [b][i], 65536 total
        if (g < BB * NN) {
            const int b = g >> 12;
            const int i = g & (NN - 1);
            const int lane = tid & 31;
            const bool valid = mask[g] != 0;
            const unsigned bal = __ballot_sync(0xffffffffu, valid);
            int base = 0;
            if (lane == 0 && bal) base = atomicAdd(&d_cnt[b], __popc(bal));
            base = __shfl_sync(0xffffffffu, base, 0);
            if (valid) {
                const int slot = base + __popc(bal & ((1u << lane) - 1u));
                float x0 = x[(b * 3 + 0) * NN + i];
                float x1 = x[(b * 3 + 1) * NN + i];
                float x2 = x[(b * 3 + 2) * NN + i];
                float y0 = y[(b * 3 + 0) * NN + i];
                float y1 = y[(b * 3 + 1) * NN + i];
                float y2 = y[(b * 3 + 2) * NN + i];
                __stcg(&d_cx[(b * 3 + 0) * NN + slot], x0);
                __stcg(&d_cx[(b * 3 + 1) * NN + slot], x1);
                __stcg(&d_cx[(b * 3 + 2) * NN + slot], x2);
                __stcg(&d_cy[(b * 3 + 0) * NN + slot], y0);
                __stcg(&d_cy[(b * 3 + 1) * NN + slot], y1);
                __stcg(&d_cy[(b * 3 + 2) * NN + slot], y2);
                __stcg(&d_nx[b * NN + slot], fmaf(x2, x2, fmaf(x1, x1, x0 * x0)));
                __stcg(&d_ny[b * NN + slot], fmaf(y2, y2, fmaf(y1, y1, y0 * y0)));
            }
        }
    }
    grid_barrier();

    // ---------- Phase 2: pairwise mins, work-stealing over 4096 units ------
    // unit u (oc slowest => heavy units pulled first, empties drain cheap):
    //   b = u&15, isplit = (u>>4)&63, dir = (u>>10)&1, oc = u>>11
    const unsigned sbase = (unsigned)__cvta_generic_to_shared(sIn);
    for (;;) {
        __syncthreads();                   // protects sIn reuse + sU
        if (tid == 0) sU = atomicAdd(&d_unit, 1);
        __syncthreads();
        const int u = sU;
        if (u >= NUNITS) break;

        const int b = u & 15;
        const int isplit = (u >> 4) & 63;
        const int dir = (u >> 10) & 1;
        const int oc = u >> 11;
        const int cnt = d_cnt[b];
        const int outer_base = oc * OUTER_PER_BLOCK;
        if (outer_base >= cnt) continue;

        const int chunk = (cnt + IS - 1) / IS;
        const int i0 = isplit * chunk;
        const int ilen = min(cnt, i0 + chunk) - i0;
        if (ilen <= 0) continue;

        const float* __restrict__ inner  = dir ? d_cx : d_cy;
        const float* __restrict__ innern = dir ? d_nx : d_ny;
        const float* __restrict__ outer  = dir ? d_cy : d_cx;
        const float* __restrict__ outern = dir ? d_ny : d_nx;

        if (tid < ilen) {                  // ilen <= 64 < NTHR
            int j = tid;
            float a = -2.f * inner[(b * 3 + 0) * NN + i0 + j];
            float c = -2.f * inner[(b * 3 + 1) * NN + i0 + j];
            float e = -2.f * inner[(b * 3 + 2) * NN + i0 + j];
            float n = innern[b * NN + i0 + j];
            sIn[2 * j]     = make_float4(a, a, c, c);
            sIn[2 * j + 1] = make_float4(e, e, n, n);
        }
        __syncthreads();

        // pack the 8 outers into 4 f32x2 pairs
        u64 ox2[OPT / 2], oy2[OPT / 2], oz2[OPT / 2];
        float xx[OPT], mn[OPT];
        #pragma unroll
        for (int p = 0; p < OPT / 2; p++) {
            int o0 = outer_base + tid + (2 * p) * NTHR;
            int o1 = o0 + NTHR;
            int c0 = (o0 < cnt) ? o0 : (cnt - 1);   // clamp; dropped at writeback
            int c1 = (o1 < cnt) ? o1 : (cnt - 1);
            ox2[p] = pack2(outer[(b * 3 + 0) * NN + c0], outer[(b * 3 + 0) * NN + c1]);
            oy2[p] = pack2(outer[(b * 3 + 1) * NN + c0], outer[(b * 3 + 1) * NN + c1]);
            oz2[p] = pack2(outer[(b * 3 + 2) * NN + c0], outer[(b * 3 + 2) * NN + c1]);
            xx[2 * p]     = outern[b * NN + c0];
            xx[2 * p + 1] = outern[b * NN + c1];
            mn[2 * p] = BIGV; mn[2 * p + 1] = BIGV;
        }

        #pragma unroll 4
        for (int j = 0; j < ilen; j++) {
            u64 ta, tc, te, tn;
            unsigned addr = sbase + (unsigned)j * 32u;
            asm volatile("ld.shared.v2.u64 {%0, %1}, [%2];"
                         : "=l"(ta), "=l"(tc) : "r"(addr));
            asm volatile("ld.shared.v2.u64 {%0, %1}, [%2];"
                         : "=l"(te), "=l"(tn) : "r"(addr + 16u));
            #pragma unroll
            for (int p = 0; p < OPT / 2; p++) {
                u64 d = fma2(ta, ox2[p], tn);      // |y|^2 - 2x.y (packed x2)
                d = fma2(tc, oy2[p], d);
                d = fma2(te, oz2[p], d);
                float lo, hi;
                unpack2(d, lo, hi);                 // register-pair rename
                mn[2 * p]     = fminf(mn[2 * p], lo);
                mn[2 * p + 1] = fminf(mn[2 * p + 1], hi);
            }
        }

        #pragma unroll
        for (int k = 0; k < OPT; k++) {
            int o = outer_base + tid + k * NTHR;
            if (o < cnt) {
                float v = fmaxf(mn[k] + xx[k], 0.f);   // >=0 so int-min == fp-min
                atomicMin((int*)&d_mins[(dir * BB + b) * NN + o],
                          __float_as_int(v));
            }
        }
    }
    grid_barrier();

    // ---------- Phase 3: per-(dir,b) masked sums. 256 units on bid<256 -----
    if (bid < 256) {
        const int db = bid >> 3;                 // dir*BB + b
        const int b = db & (BB - 1);
        const int chunk = bid & 7;
        const int cnt = d_cnt[b];
        const int base = chunk * 512 + tid * 2;

        float2 v = __ldcg((const float2*)&d_mins[db * NN + base]);
        float s = ((base < cnt) ? v.x : 0.f) + ((base + 1 < cnt) ? v.y : 0.f);
        #pragma unroll
        for (int off = 16; off; off >>= 1)
            s += __shfl_xor_sync(0xffffffffu, s, off);
        if ((tid & 31) == 0) sRed[tid >> 5] = s;
        __syncthreads();
        if (tid == 0) {
            float bs = 0.f;
            #pragma unroll
            for (int i = 0; i < NTHR / 32; i++) bs += sRed[i];
            atomicAdd(&d_sums[db], bs);
        }
    }
    grid_barrier();

    // ---------- Phase 4: parallel finalize ---------------------------------
    if (bid == 0 && tid < 32) {
        float v = __ldcg(&d_sums[tid]) / (float)__ldcg(&d_cnt[tid & (BB - 1)]);
        #pragma unroll
        for (int off = 16; off; off >>= 1)
            v += __shfl_xor_sync(0xffffffffu, v, off);
        if (tid == 0) out[0] = v / (float)BB;
    }
}

extern "C" void kernel_launch(void* const* d_in, const int* in_sizes, int n_in,
                              void* d_out, int out_size) {
    const float* x    = (const float*)d_in[0];
    const float* y    = (const float*)d_in[1];
    const int*   mask = (const int*)d_in[2];
    float* out = (float*)d_out;

    k_fused<<<NBLK, NTHR>>>(x, y, mask, out);
}

// round 16
// speedup vs baseline: 1.2178x; 1.2178x over previous
#include <cuda_runtime.h>

// GAEChamferLoss: B=16, C=3, N=4096, mask in {0,1}. Single fused persistent
// kernel: compact -> pairwise-min -> reduce+finalize, with only TWO software
// grid barriers (592 co-resident blocks, 4 per SM).
// d = |x|^2 + |y|^2 - 2 x.y; |y|^2 folded into the FMA chain, |x|^2 added
// after the min. Hot loop: packed fma.rn.f32x2, 4 outers/thread (2 packed
// pairs), inner tile pre-duplicated in smem.
// Mins are stored as enc = ~bits(d) with atomicMax(unsigned): larger enc ==
// smaller d, and the static zero-init loses to every real write -> no init
// pass needed. Each phase's last reader restores state for graph replay.

#define BB 16
#define NN 4096
#define BIGV 1e10f

#define NBLK 592                   // 4 x 148 (all resident on 148/152-SM parts)
#define NTHR 256
#define IS 32                      // inner splits
#define OC 4                       // outer chunks of 1024 (covers cnt<=4096)
#define OPT 4                      // outers per thread (2 packed pairs)
#define OUTER_PER_BLOCK (NTHR * OPT)   // 1024
#define MAX_INNER ((NN + IS - 1) / IS) // 128 worst case
#define NUNITS (OC * 2 * IS * BB)      // 4096

typedef unsigned long long u64;
typedef unsigned int u32;

__device__ __forceinline__ u64 pack2(float lo, float hi) {
    u64 r; asm("mov.b64 %0, {%1, %2};" : "=l"(r) : "f"(lo), "f"(hi)); return r;
}
__device__ __forceinline__ u64 fma2(u64 a, u64 b, u64 c) {
    u64 d;
    asm("fma.rn.f32x2 %0, %1, %2, %3;" : "=l"(d) : "l"(a), "l"(b), "l"(c));
    return d;
}
__device__ __forceinline__ void unpack2(u64 v, float& lo, float& hi) {
    asm("mov.b64 {%0, %1}, %2;" : "=f"(lo), "=f"(hi) : "l"(v));
}

// Scratch (device globals, zero-initialized — no allocations allowed)
__device__ float d_cx[BB * 3 * NN];
__device__ float d_cy[BB * 3 * NN];
__device__ float d_nx[BB * NN];
__device__ float d_ny[BB * NN];
__device__ int   d_cnt[BB];
__device__ __align__(16) u32 d_minu[2 * BB * NN];  // enc = ~bits(d); 0 = empty
__device__ float d_sums[2 * BB];
__device__ int   d_unit;                   // work-steal cursor
__device__ int   d_done;                   // phase-3 ticket
__device__ unsigned d_bar_arrive;
__device__ volatile unsigned d_bar_gen;

__device__ __forceinline__ void grid_barrier() {
    __syncthreads();
    __threadfence();
    if (threadIdx.x == 0) {
        unsigned gen = d_bar_gen;
        if (atomicAdd(&d_bar_arrive, 1u) == NBLK - 1) {
            atomicExch(&d_bar_arrive, 0u);
            __threadfence();
            d_bar_gen = gen + 1;
        } else {
            while (d_bar_gen == gen) { }
        }
    }
    __syncthreads();
}

__global__ __launch_bounds__(NTHR, 4)
void k_fused(const float* __restrict__ x, const float* __restrict__ y,
             const int* __restrict__ mask, float* __restrict__ out)
{
    const int tid = threadIdx.x;
    const int bid = blockIdx.x;
    // per inner point: two float4s = {-2a,-2a,-2c,-2c} and {-2e,-2e, n, n}
    __shared__ float4 sIn[2 * MAX_INNER];          // 4 KB
    __shared__ float sRed[NTHR / 32];
    __shared__ int sU;
    __shared__ int sLast;

    // ---------- Phase 1: warp-aggregated compaction + norms ----------------
    // (d_cnt is 0 here: static zero-init on first call, reset by the
    //  finalizer at the end of every call thereafter.)
    {
        const int g = bid * NTHR + tid;             // [b][i], 65536 total
        if (g < BB * NN) {
            const int b = g >> 12;
            const int i = g & (NN - 1);
            const int lane = tid & 31;
            const bool valid = mask[g] != 0;
            const unsigned bal = __ballot_sync(0xffffffffu, valid);
            int base = 0;
            if (lane == 0 && bal) base = atomicAdd(&d_cnt[b], __popc(bal));
            base = __shfl_sync(0xffffffffu, base, 0);
            if (valid) {
                const int slot = base + __popc(bal & ((1u << lane) - 1u));
                float x0 = x[(b * 3 + 0) * NN + i];
                float x1 = x[(b * 3 + 1) * NN + i];
                float x2 = x[(b * 3 + 2) * NN + i];
                float y0 = y[(b * 3 + 0) * NN + i];
                float y1 = y[(b * 3 + 1) * NN + i];
                float y2 = y[(b * 3 + 2) * NN + i];
                __stcg(&d_cx[(b * 3 + 0) * NN + slot], x0);
                __stcg(&d_cx[(b * 3 + 1) * NN + slot], x1);
                __stcg(&d_cx[(b * 3 + 2) * NN + slot], x2);
                __stcg(&d_cy[(b * 3 + 0) * NN + slot], y0);
                __stcg(&d_cy[(b * 3 + 1) * NN + slot], y1);
                __stcg(&d_cy[(b * 3 + 2) * NN + slot], y2);
                __stcg(&d_nx[b * NN + slot], fmaf(x2, x2, fmaf(x1, x1, x0 * x0)));
                __stcg(&d_ny[b * NN + slot], fmaf(y2, y2, fmaf(y1, y1, y0 * y0)));
            }
        }
    }
    grid_barrier();

    // ---------- Phase 2: pairwise mins, work-stealing over 4096 units ------
    // unit u (oc slowest => heavy units pulled first, empties drain cheap):
    //   b = u&15, isplit = (u>>4)&31, dir = (u>>9)&1, oc = u>>10
    const unsigned sbase = (unsigned)__cvta_generic_to_shared(sIn);
    for (;;) {
        __syncthreads();                   // protects sIn reuse + sU
        if (tid == 0) sU = atomicAdd(&d_unit, 1);
        __syncthreads();
        const int u = sU;
        if (u >= NUNITS) break;

        const int b = u & 15;
        const int isplit = (u >> 4) & 31;
        const int dir = (u >> 9) & 1;
        const int oc = u >> 10;
        const int cnt = d_cnt[b];
        const int outer_base = oc * OUTER_PER_BLOCK;
        if (outer_base >= cnt) continue;

        const int chunk = (cnt + IS - 1) / IS;
        const int i0 = isplit * chunk;
        const int ilen = min(cnt, i0 + chunk) - i0;
        if (ilen <= 0) continue;

        const float* __restrict__ inner  = dir ? d_cx : d_cy;
        const float* __restrict__ innern = dir ? d_nx : d_ny;
        const float* __restrict__ outer  = dir ? d_cy : d_cx;
        const float* __restrict__ outern = dir ? d_ny : d_nx;

        if (tid < ilen) {                  // ilen <= 128 < NTHR
            int j = tid;
            float a = -2.f * inner[(b * 3 + 0) * NN + i0 + j];
            float c = -2.f * inner[(b * 3 + 1) * NN + i0 + j];
            float e = -2.f * inner[(b * 3 + 2) * NN + i0 + j];
            float n = innern[b * NN + i0 + j];
            sIn[2 * j]     = make_float4(a, a, c, c);
            sIn[2 * j + 1] = make_float4(e, e, n, n);
        }
        __syncthreads();

        // pack the 4 outers into 2 f32x2 pairs
        u64 ox2[2], oy2[2], oz2[2];
        float xx[OPT], mn[OPT];
        #pragma unroll
        for (int p = 0; p < 2; p++) {
            int o0 = outer_base + tid + (2 * p) * NTHR;
            int o1 = o0 + NTHR;
            int c0 = (o0 < cnt) ? o0 : (cnt - 1);   // clamp; dropped at writeback
            int c1 = (o1 < cnt) ? o1 : (cnt - 1);
            ox2[p] = pack2(outer[(b * 3 + 0) * NN + c0], outer[(b * 3 + 0) * NN + c1]);
            oy2[p] = pack2(outer[(b * 3 + 1) * NN + c0], outer[(b * 3 + 1) * NN + c1]);
            oz2[p] = pack2(outer[(b * 3 + 2) * NN + c0], outer[(b * 3 + 2) * NN + c1]);
            xx[2 * p]     = outern[b * NN + c0];
            xx[2 * p + 1] = outern[b * NN + c1];
            mn[2 * p] = BIGV; mn[2 * p + 1] = BIGV;
        }

        #pragma unroll 4
        for (int j = 0; j < ilen; j++) {
            u64 ta, tc, te, tn;
            unsigned addr = sbase + (unsigned)j * 32u;
            asm volatile("ld.shared.v2.u64 {%0, %1}, [%2];"
                         : "=l"(ta), "=l"(tc) : "r"(addr));
            asm volatile("ld.shared.v2.u64 {%0, %1}, [%2];"
                         : "=l"(te), "=l"(tn) : "r"(addr + 16u));
            #pragma unroll
            for (int p = 0; p < 2; p++) {
                u64 d = fma2(ta, ox2[p], tn);      // |y|^2 - 2x.y (packed x2)
                d = fma2(tc, oy2[p], d);
                d = fma2(te, oz2[p], d);
                float lo, hi;
                unpack2(d, lo, hi);                 // register-pair rename
                mn[2 * p]     = fminf(mn[2 * p], lo);
                mn[2 * p + 1] = fminf(mn[2 * p + 1], hi);
            }
        }

        #pragma unroll
        for (int k = 0; k < OPT; k++) {
            int o = outer_base + tid + k * NTHR;
            if (o < cnt) {
                float v = fmaxf(mn[k] + xx[k], 0.f);   // v >= 0
                // enc = ~bits(v): larger enc <=> smaller v; 0 = "empty"
                atomicMax(&d_minu[(dir * BB + b) * NN + o],
                          ~__float_as_uint(v));
            }
        }
    }
    grid_barrier();

    // ---------- Phase 3: per-(dir,b) sums + in-place finalize --------------
    if (bid < 256) {
        const int db = bid >> 3;                 // dir*BB + b
        const int b = db & (BB - 1);
        const int cnt = d_cnt[b];
        const int base = (bid & 7) * 512 + tid * 2;

        uint2 v = __ldcg((const uint2*)&d_minu[db * NN + base]);
        float s = 0.f;
        if (base < cnt)     s += __uint_as_float(~v.x);
        if (base + 1 < cnt) s += __uint_as_float(~v.y);
        // restore zero-state for the next graph replay
        __stcg((uint2*)&d_minu[db * NN + base], make_uint2(0u, 0u));

        #pragma unroll
        for (int off = 16; off; off >>= 1)
            s += __shfl_xor_sync(0xffffffffu, s, off);
        if ((tid & 31) == 0) sRed[tid >> 5] = s;
        __syncthreads();
        if (tid == 0) {
            float bs = 0.f;
            #pragma unroll
            for (int i = 0; i < NTHR / 32; i++) bs += sRed[i];
            atomicAdd(&d_sums[db], bs);
            __threadfence();
            sLast = (atomicAdd(&d_done, 1) == 255);
        }
        __syncthreads();

        // ---------- Phase 4: the 256th block finalizes + resets state ------
        if (sLast) {
            if (tid < 32) {
                float sv = __ldcg(&d_sums[tid]);
                float cv = (float)__ldcg(&d_cnt[tid & (BB - 1)]);
                float r = sv / cv;
                #pragma unroll
                for (int off = 16; off; off >>= 1)
                    r += __shfl_xor_sync(0xffffffffu, r, off);
                if (tid == 0) out[0] = r / (float)BB;
                __stcg(&d_sums[tid], 0.f);          // reset after read
            }
            if (tid < BB) __stcg(&d_cnt[tid], 0);
            if (tid == 0) { __stcg(&d_unit, 0); __stcg(&d_done, 0); }
        }
    }
}

extern "C" void kernel_launch(void* const* d_in, const int* in_sizes, int n_in,
                              void* d_out, int out_size) {
    const float* x    = (const float*)d_in[0];
    const float* y    = (const float*)d_in[1];
    const int*   mask = (const int*)d_in[2];
    float* out = (float*)d_out;

    k_fused<<<NBLK, NTHR>>>(x, y, mask, out);
}

// round 17
// speedup vs baseline: 1.2855x; 1.0556x over previous
#include <cuda_runtime.h>

// GAEChamferLoss: B=16, C=3, N=4096, mask in {0,1}. Single fused persistent
// kernel: compact -> pairwise-min -> reduce+finalize, TWO software grid
// barriers (592 co-resident blocks, 4 per SM).
// d = |x|^2 + |y|^2 - 2 x.y; |y|^2 folded into the FMA chain, |x|^2 added
// after the min. Hot loop: packed fma.rn.f32x2, 4 outers/thread (2 packed
// pairs), inner tile pre-duplicated in smem, and a 1-deep software pipeline
// (prefetch j+1's LDS while computing j) to hide the 29-cyc LDS latency.
// Mins stored as enc = ~bits(d) via red.global.max.u32 (no-return reduction):
// larger enc == smaller d, zero-init loses to every real write -> no init
// pass. Each phase's last reader restores state for graph replay.

#define BB 16
#define NN 4096
#define BIGV 1e10f

#define NBLK 592                   // 4 x 148 (all resident on 148/152-SM parts)
#define NTHR 256
#define IS 32                      // inner splits
#define OC 4                       // outer chunks of 1024 (covers cnt<=4096)
#define OPT 4                      // outers per thread (2 packed pairs)
#define OUTER_PER_BLOCK (NTHR * OPT)   // 1024
#define MAX_INNER ((NN + IS - 1) / IS) // 128 worst case
#define NUNITS (OC * 2 * IS * BB)      // 4096

typedef unsigned long long u64;
typedef unsigned int u32;

__device__ __forceinline__ u64 pack2(float lo, float hi) {
    u64 r; asm("mov.b64 %0, {%1, %2};" : "=l"(r) : "f"(lo), "f"(hi)); return r;
}
__device__ __forceinline__ u64 fma2(u64 a, u64 b, u64 c) {
    u64 d;
    asm("fma.rn.f32x2 %0, %1, %2, %3;" : "=l"(d) : "l"(a), "l"(b), "l"(c));
    return d;
}
__device__ __forceinline__ void unpack2(u64 v, float& lo, float& hi) {
    asm("mov.b64 {%0, %1}, %2;" : "=f"(lo), "=f"(hi) : "l"(v));
}
__device__ __forceinline__ void red_max_u32(u32* p, u32 v) {
    asm volatile("red.global.max.u32 [%0], %1;" :: "l"(p), "r"(v) : "memory");
}

// Scratch (device globals, zero-initialized — no allocations allowed)
__device__ float d_cx[BB * 3 * NN];
__device__ float d_cy[BB * 3 * NN];
__device__ float d_nx[BB * NN];
__device__ float d_ny[BB * NN];
__device__ int   d_cnt[BB];
__device__ __align__(16) u32 d_minu[2 * BB * NN];  // enc = ~bits(d); 0 = empty
__device__ float d_sums[2 * BB];
__device__ int   d_unit;                   // work-steal cursor
__device__ int   d_done;                   // phase-3 ticket
__device__ unsigned d_bar_arrive;
__device__ volatile unsigned d_bar_gen;

__device__ __forceinline__ void grid_barrier() {
    __syncthreads();
    __threadfence();
    if (threadIdx.x == 0) {
        unsigned gen = d_bar_gen;
        if (atomicAdd(&d_bar_arrive, 1u) == NBLK - 1) {
            atomicExch(&d_bar_arrive, 0u);
            __threadfence();
            d_bar_gen = gen + 1;
        } else {
            while (d_bar_gen == gen) { }
        }
    }
    __syncthreads();
}

__global__ __launch_bounds__(NTHR, 4)
void k_fused(const float* __restrict__ x, const float* __restrict__ y,
             const int* __restrict__ mask, float* __restrict__ out)
{
    const int tid = threadIdx.x;
    const int bid = blockIdx.x;
    // per inner point: two float4s = {-2a,-2a,-2c,-2c} and {-2e,-2e, n, n}
    // +2 pad entries so the last pipeline prefetch stays in-bounds
    __shared__ float4 sIn[2 * MAX_INNER + 2];      // ~4 KB
    __shared__ float sRed[NTHR / 32];
    __shared__ int sU;
    __shared__ int sLast;

    // ---------- Phase 1: warp-aggregated compaction + norms ----------------
    // (d_cnt is 0 here: static zero-init on first call, reset by the
    //  finalizer at the end of every call thereafter.)
    {
        const int g = bid * NTHR + tid;             // [b][i], 65536 total
        if (g < BB * NN) {
            const int b = g >> 12;
            const int i = g & (NN - 1);
            const int lane = tid & 31;
            const bool valid = mask[g] != 0;
            const unsigned bal = __ballot_sync(0xffffffffu, valid);
            int base = 0;
            if (lane == 0 && bal) base = atomicAdd(&d_cnt[b], __popc(bal));
            base = __shfl_sync(0xffffffffu, base, 0);
            if (valid) {
                const int slot = base + __popc(bal & ((1u << lane) - 1u));
                float x0 = x[(b * 3 + 0) * NN + i];
                float x1 = x[(b * 3 + 1) * NN + i];
                float x2 = x[(b * 3 + 2) * NN + i];
                float y0 = y[(b * 3 + 0) * NN + i];
                float y1 = y[(b * 3 + 1) * NN + i];
                float y2 = y[(b * 3 + 2) * NN + i];
                __stcg(&d_cx[(b * 3 + 0) * NN + slot], x0);
                __stcg(&d_cx[(b * 3 + 1) * NN + slot], x1);
                __stcg(&d_cx[(b * 3 + 2) * NN + slot], x2);
                __stcg(&d_cy[(b * 3 + 0) * NN + slot], y0);
                __stcg(&d_cy[(b * 3 + 1) * NN + slot], y1);
                __stcg(&d_cy[(b * 3 + 2) * NN + slot], y2);
                __stcg(&d_nx[b * NN + slot], fmaf(x2, x2, fmaf(x1, x1, x0 * x0)));
                __stcg(&d_ny[b * NN + slot], fmaf(y2, y2, fmaf(y1, y1, y0 * y0)));
            }
        }
    }
    grid_barrier();

    // ---------- Phase 2: pairwise mins, work-stealing over 4096 units ------
    // unit u (oc slowest => heavy units pulled first, empties drain cheap):
    //   b = u&15, isplit = (u>>4)&31, dir = (u>>9)&1, oc = u>>10
    const unsigned sbase = (unsigned)__cvta_generic_to_shared(sIn);
    for (;;) {
        __syncthreads();                   // protects sIn reuse + sU
        if (tid == 0) sU = atomicAdd(&d_unit, 1);
        __syncthreads();
        const int u = sU;
        if (u >= NUNITS) break;

        const int b = u & 15;
        const int isplit = (u >> 4) & 31;
        const int dir = (u >> 9) & 1;
        const int oc = u >> 10;
        const int cnt = d_cnt[b];
        const int outer_base = oc * OUTER_PER_BLOCK;
        if (outer_base >= cnt) continue;

        const int chunk = (cnt + IS - 1) / IS;
        const int i0 = isplit * chunk;
        const int ilen = min(cnt, i0 + chunk) - i0;
        if (ilen <= 0) continue;

        const float* __restrict__ inner  = dir ? d_cx : d_cy;
        const float* __restrict__ innern = dir ? d_nx : d_ny;
        const float* __restrict__ outer  = dir ? d_cy : d_cx;
        const float* __restrict__ outern = dir ? d_ny : d_nx;

        if (tid < ilen) {                  // ilen <= 128 < NTHR
            int j = tid;
            float a = -2.f * inner[(b * 3 + 0) * NN + i0 + j];
            float c = -2.f * inner[(b * 3 + 1) * NN + i0 + j];
            float e = -2.f * inner[(b * 3 + 2) * NN + i0 + j];
            float n = innern[b * NN + i0 + j];
            sIn[2 * j]     = make_float4(a, a, c, c);
            sIn[2 * j + 1] = make_float4(e, e, n, n);
        }
        __syncthreads();

        // pack the 4 outers into 2 f32x2 pairs
        u64 ox2[2], oy2[2], oz2[2];
        float xx[OPT], mn[OPT];
        #pragma unroll
        for (int p = 0; p < 2; p++) {
            int o0 = outer_base + tid + (2 * p) * NTHR;
            int o1 = o0 + NTHR;
            int c0 = (o0 < cnt) ? o0 : (cnt - 1);   // clamp; dropped at writeback
            int c1 = (o1 < cnt) ? o1 : (cnt - 1);
            ox2[p] = pack2(outer[(b * 3 + 0) * NN + c0], outer[(b * 3 + 0) * NN + c1]);
            oy2[p] = pack2(outer[(b * 3 + 1) * NN + c0], outer[(b * 3 + 1) * NN + c1]);
            oz2[p] = pack2(outer[(b * 3 + 2) * NN + c0], outer[(b * 3 + 2) * NN + c1]);
            xx[2 * p]     = outern[b * NN + c0];
            xx[2 * p + 1] = outern[b * NN + c1];
            mn[2 * p] = BIGV; mn[2 * p + 1] = BIGV;
        }

        // 1-deep software pipeline: prefetch j+1 while computing j.
        unsigned addr = sbase;
        u64 ta, tc, te, tn;
        asm("ld.shared.v2.u64 {%0, %1}, [%2];"
            : "=l"(ta), "=l"(tc) : "r"(addr));
        asm("ld.shared.v2.u64 {%0, %1}, [%2];"
            : "=l"(te), "=l"(tn) : "r"(addr + 16u));
        #pragma unroll 2
        for (int j = 0; j < ilen; j++) {
            const u64 ca = ta, cc = tc, ce = te, cn = tn;
            addr += 32u;
            // prefetch (last iteration reads the pad entries; never consumed)
            asm("ld.shared.v2.u64 {%0, %1}, [%2];"
                : "=l"(ta), "=l"(tc) : "r"(addr));
            asm("ld.shared.v2.u64 {%0, %1}, [%2];"
                : "=l"(te), "=l"(tn) : "r"(addr + 16u));
            #pragma unroll
            for (int p = 0; p < 2; p++) {
                u64 d = fma2(ca, ox2[p], cn);      // |y|^2 - 2x.y (packed x2)
                d = fma2(cc, oy2[p], d);
                d = fma2(ce, oz2[p], d);
                float lo, hi;
                unpack2(d, lo, hi);                 // register-pair rename
                mn[2 * p]     = fminf(mn[2 * p], lo);
                mn[2 * p + 1] = fminf(mn[2 * p + 1], hi);
            }
        }

        #pragma unroll
        for (int k = 0; k < OPT; k++) {
            int o = outer_base + tid + k * NTHR;
            if (o < cnt) {
                float v = fmaxf(mn[k] + xx[k], 0.f);   // v >= 0
                // enc = ~bits(v): larger enc <=> smaller v; 0 = "empty"
                red_max_u32(&d_minu[(dir * BB + b) * NN + o],
                            ~__float_as_uint(v));
            }
        }
    }
    grid_barrier();

    // ---------- Phase 3: per-(dir,b) sums + in-place finalize --------------
    if (bid < 256) {
        const int db = bid >> 3;                 // dir*BB + b
        const int b = db & (BB - 1);
        const int cnt = d_cnt[b];
        const int base = (bid & 7) * 512 + tid * 2;

        uint2 v = __ldcg((const uint2*)&d_minu[db * NN + base]);
        float s = 0.f;
        if (base < cnt)     s += __uint_as_float(~v.x);
        if (base + 1 < cnt) s += __uint_as_float(~v.y);
        // restore zero-state for the next graph replay
        __stcg((uint2*)&d_minu[db * NN + base], make_uint2(0u, 0u));

        #pragma unroll
        for (int off = 16; off; off >>= 1)
            s += __shfl_xor_sync(0xffffffffu, s, off);
        if ((tid & 31) == 0) sRed[tid >> 5] = s;
        __syncthreads();
        if (tid == 0) {
            float bs = 0.f;
            #pragma unroll
            for (int i = 0; i < NTHR / 32; i++) bs += sRed[i];
            atomicAdd(&d_sums[db], bs);
            __threadfence();
            sLast = (atomicAdd(&d_done, 1) == 255);
        }
        __syncthreads();

        // ---------- Phase 4: the 256th block finalizes + resets state ------
        if (sLast) {
            if (tid < 32) {
                float sv = __ldcg(&d_sums[tid]);
                float cv = (float)__ldcg(&d_cnt[tid & (BB - 1)]);
                float r = sv / cv;
                #pragma unroll
                for (int off = 16; off; off >>= 1)
                    r += __shfl_xor_sync(0xffffffffu, r, off);
                if (tid == 0) out[0] = r / (float)BB;
                __stcg(&d_sums[tid], 0.f);          // reset after read
            }
            if (tid < BB) __stcg(&d_cnt[tid], 0);
            if (tid == 0) { __stcg(&d_unit, 0); __stcg(&d_done, 0); }
        }
    }
}

extern "C" void kernel_launch(void* const* d_in, const int* in_sizes, int n_in,
                              void* d_out, int out_size) {
    const float* x    = (const float*)d_in[0];
    const float* y    = (const float*)d_in[1];
    const int*   mask = (const int*)d_in[2];
    float* out = (float*)d_out;

    k_fused<<<NBLK, NTHR>>>(x, y, mask, out);
}